// round 5
// baseline (speedup 1.0000x reference)
#include <cuda_runtime.h>
#include <math.h>

// CropAndResize: x [B,H,W,C=4] fp32, boxes [B,4] (y1,x1,y2,x2 in [0,1]),
// output [B,crop,crop,4] fp32 bilinear.
//
// Warp-cooperative separable kernel. Each warp owns 32 consecutive output
// pixels of one output row:
//   - source rows t/b are warp-uniform (in_y depends only on the row)
//   - the x-window the warp samples spans <= ~147 float4s (box width <= W)
//   - warp loads the window from rows t and b fully coalesced, v-lerps into
//     a per-warp smem buffer, __syncwarp, then lanes h-lerp via LDS + STG.
// Removes the scattered 4-corner gather L1tex replays without block-level
// sync or load imbalance (fixed 32 px per warp).

#define WPB 8          // warps per block
#define SPAN_MAX 160   // >= max window: ceil(1023/223 * 31) + 3 = 147

__global__ __launch_bounds__(WPB * 32)
void crop_resize_warp_kernel(const float* __restrict__ x,
                             const float* __restrict__ boxes,
                             float* __restrict__ out,
                             int H, int W, int crop, int chunks, int nwarps) {
    __shared__ float4 buf[WPB][SPAN_MAX];

    const int wid  = threadIdx.x >> 5;
    const int lane = threadIdx.x & 31;
    const int gw   = blockIdx.x * WPB + wid;
    if (gw >= nwarps) return;

    const int per_b = crop * chunks;
    const int b     = gw / per_b;
    const int rem   = gw - b * per_b;
    const int r     = rem / chunks;
    const int c0    = (rem - r * chunks) << 5;

    const float y1 = boxes[b * 4 + 0];
    const float x1 = boxes[b * 4 + 1];
    const float y2 = boxes[b * 4 + 2];
    const float x2 = boxes[b * 4 + 3];

    const float inv = 1.0f / (float)(crop - 1);
    const float hm1 = (float)(H - 1);
    const float wm1 = (float)(W - 1);

    float4* __restrict__ outrow =
        (float4*)(out) + ((size_t)b * crop + r) * crop;

    // ---- vertical (warp-uniform) ----
    const float in_y = (y1 + (float)r * inv * (y2 - y1)) * hm1;
    const bool valid_y = (in_y >= 0.0f) && (in_y <= hm1);

    const int c = c0 + lane;
    const bool live = (c < crop);

    if (!valid_y) {
        if (live) outrow[c] = make_float4(0.f, 0.f, 0.f, 0.f);
        return;
    }

    const float top_f = floorf(in_y);
    const float yl = in_y - top_f;
    const int t  = min(max((int)top_f, 0), H - 1);
    const int bo = min(t + 1, H - 1);

    // ---- per-lane horizontal position ----
    const int c_eff = live ? c : (crop - 1);
    const float in_x = (x1 + (float)c_eff * inv * (x2 - x1)) * wm1;
    const bool valid_x = (in_x >= 0.0f) && (in_x <= wm1);

    const float left_f = floorf(in_x);
    const float xl = in_x - left_f;
    const int l  = min(max((int)left_f, 0), W - 1);
    const int rr = min(l + 1, W - 1);

    // ---- warp window [lo..hi] (in_x nondecreasing since x2>=x1) ----
    const int last_lane = min(31, crop - 1 - c0);
    int lo = __shfl_sync(0xffffffffu, l,  0);
    int hi = __shfl_sync(0xffffffffu, rr, last_lane);
    lo = min(lo, l);            // safety under fp edge cases
    hi = max(hi, rr);
    const int span = hi - lo + 1;

    const float4* __restrict__ rowT = (const float4*)(x) + ((size_t)b * H + t)  * W;
    const float4* __restrict__ rowB = (const float4*)(x) + ((size_t)b * H + bo) * W;

    float4 vl4, vr4;
    if (span <= SPAN_MAX) {
        // cooperative coalesced load + vertical lerp into smem
        float4* wbuf = buf[wid];
        for (int i = lane; i < span; i += 32) {
            const float4 vt = __ldg(rowT + lo + i);
            const float4 vb = __ldg(rowB + lo + i);
            float4 v;
            v.x = fmaf(vb.x - vt.x, yl, vt.x);
            v.y = fmaf(vb.y - vt.y, yl, vt.y);
            v.z = fmaf(vb.z - vt.z, yl, vt.z);
            v.w = fmaf(vb.w - vt.w, yl, vt.w);
            wbuf[i] = v;
        }
        __syncwarp();
        vl4 = wbuf[l  - lo];
        vr4 = wbuf[rr - lo];
    } else {
        // fallback (cannot trigger for these shapes): direct gathers
        const float4 tl = __ldg(rowT + l);
        const float4 tr = __ldg(rowT + rr);
        const float4 bl = __ldg(rowB + l);
        const float4 br = __ldg(rowB + rr);
        vl4.x = fmaf(bl.x - tl.x, yl, tl.x);
        vl4.y = fmaf(bl.y - tl.y, yl, tl.y);
        vl4.z = fmaf(bl.z - tl.z, yl, tl.z);
        vl4.w = fmaf(bl.w - tl.w, yl, tl.w);
        vr4.x = fmaf(br.x - tr.x, yl, tr.x);
        vr4.y = fmaf(br.y - tr.y, yl, tr.y);
        vr4.z = fmaf(br.z - tr.z, yl, tr.z);
        vr4.w = fmaf(br.w - tr.w, yl, tr.w);
    }

    if (!live) return;

    float4 res = make_float4(0.f, 0.f, 0.f, 0.f);
    if (valid_x) {
        res.x = fmaf(vr4.x - vl4.x, xl, vl4.x);
        res.y = fmaf(vr4.y - vl4.y, xl, vl4.y);
        res.z = fmaf(vr4.z - vl4.z, xl, vl4.z);
        res.w = fmaf(vr4.w - vl4.w, xl, vl4.w);
    }
    outrow[c] = res;
}

extern "C" void kernel_launch(void* const* d_in, const int* in_sizes, int n_in,
                              void* d_out, int out_size) {
    const float* x     = (const float*)d_in[0];
    const float* boxes = (const float*)d_in[1];
    float* out = (float*)d_out;

    const int B = in_sizes[1] / 4;          // boxes is [B,4]
    const int C = 4;
    const long long hw = (long long)in_sizes[0] / ((long long)B * C);
    int H = (int)(sqrt((double)hw) + 0.5);
    int W = H;
    const long long cc = (long long)out_size / ((long long)B * C);
    int crop = (int)(sqrt((double)cc) + 0.5);

    const int chunks = (crop + 31) / 32;
    const int nwarps = B * crop * chunks;
    const int blocks = (nwarps + WPB - 1) / WPB;
    crop_resize_warp_kernel<<<blocks, WPB * 32>>>(x, boxes, out, H, W, crop,
                                                  chunks, nwarps);
}